// round 16
// baseline (speedup 1.0000x reference)
#include <cuda_runtime.h>
#include <cuda_bf16.h>
#include <stdint.h>

#define B_   4
#define S_   2048
#define D_   512
#define H_   8
#define HD_  64
#define ROWS_ (B_ * S_)          // 8192
#define EPS_ 1e-8f

// ---------------------------------------------------------------------------
// Scratch (__device__ globals; allocations are forbidden)
// ---------------------------------------------------------------------------
__device__ unsigned short g_Gh[(size_t)ROWS_ * D_];
__device__ unsigned short g_Gl[(size_t)ROWS_ * D_];
__device__ unsigned short g_Eh[(size_t)ROWS_ * D_];
__device__ unsigned short g_El[(size_t)ROWS_ * D_];
__device__ unsigned short g_Qh[(size_t)ROWS_ * D_];
__device__ unsigned short g_Ql[(size_t)ROWS_ * D_];
__device__ unsigned short g_Kh[(size_t)ROWS_ * D_];
__device__ unsigned short g_Kl[(size_t)ROWS_ * D_];
__device__ unsigned short g_Vh[(size_t)ROWS_ * D_];
__device__ unsigned short g_Vl[(size_t)ROWS_ * D_];
__device__ unsigned short g_Ah[(size_t)ROWS_ * D_];
__device__ unsigned short g_Al[(size_t)ROWS_ * D_];
// Wf split row-major [1024][512] (A operand of weight products)
__device__ unsigned short g_Wfrm_h[(size_t)(2 * D_) * D_];
__device__ unsigned short g_Wfrm_l[(size_t)(2 * D_) * D_];
// weight [N][K] hi/lo splits
__device__ unsigned short g_Wq_h[(size_t)D_ * D_];
__device__ unsigned short g_Wq_l[(size_t)D_ * D_];
__device__ unsigned short g_Wk_h[(size_t)D_ * D_];
__device__ unsigned short g_Wk_l[(size_t)D_ * D_];
__device__ unsigned short g_Wv_h[(size_t)D_ * D_];
__device__ unsigned short g_Wv_l[(size_t)D_ * D_];
__device__ unsigned short g_Wo_h[(size_t)D_ * D_];
__device__ unsigned short g_Wo_l[(size_t)D_ * D_];
// folded weight products (Wf@Wq)*(1/8), Wf@Wk as [N=512][K=1024] hi/lo
__device__ unsigned short g_Pq_h[(size_t)D_ * 2 * D_];
__device__ unsigned short g_Pq_l[(size_t)D_ * 2 * D_];
__device__ unsigned short g_Pk_h[(size_t)D_ * 2 * D_];
__device__ unsigned short g_Pk_l[(size_t)D_ * 2 * D_];
// folded biases
__device__ float g_bfq[D_];
__device__ float g_bfk[D_];
__device__ float g_zero[D_];   // zero-initialized, never written

// ---------------------------------------------------------------------------
// sm_80-level PTX helpers (NO tcgen05 — build target is plain sm_103)
// ---------------------------------------------------------------------------
__device__ __forceinline__ uint32_t smem_u32(const void* p) {
    uint32_t a;
    asm("{ .reg .u64 t; cvta.to.shared.u64 t, %1; cvt.u32.u64 %0, t; }"
        : "=r"(a) : "l"(p));
    return a;
}
__device__ __forceinline__ void ldm4(uint32_t addr, uint32_t* r) {
    asm volatile("ldmatrix.sync.aligned.m8n8.x4.shared.b16 {%0,%1,%2,%3}, [%4];"
                 : "=r"(r[0]), "=r"(r[1]), "=r"(r[2]), "=r"(r[3]) : "r"(addr));
}
__device__ __forceinline__ void ldm4t(uint32_t addr, uint32_t* r) {
    asm volatile("ldmatrix.sync.aligned.m8n8.x4.trans.shared.b16 {%0,%1,%2,%3}, [%4];"
                 : "=r"(r[0]), "=r"(r[1]), "=r"(r[2]), "=r"(r[3]) : "r"(addr));
}
__device__ __forceinline__ void mma_bf16(float* c, const uint32_t* a,
                                         const uint32_t* b) {
    asm volatile("mma.sync.aligned.m16n8k16.row.col.f32.bf16.bf16.f32 "
                 "{%0,%1,%2,%3}, {%4,%5,%6,%7}, {%8,%9}, {%0,%1,%2,%3};"
                 : "+f"(c[0]), "+f"(c[1]), "+f"(c[2]), "+f"(c[3])
                 : "r"(a[0]), "r"(a[1]), "r"(a[2]), "r"(a[3]),
                   "r"(b[0]), "r"(b[1]));
}
#define CP_ASYNC16(dst, src) \
    asm volatile("cp.async.ca.shared.global [%0], [%1], 16;" \
                 :: "r"(dst), "l"(src))
#define CP_COMMIT() asm volatile("cp.async.commit_group;" ::: "memory")
#define CP_WAIT0()  asm volatile("cp.async.wait_group 0;" ::: "memory")
#define CP_WAIT1()  asm volatile("cp.async.wait_group 1;" ::: "memory")

__device__ __forceinline__ void bsplit(float v, unsigned short& h,
                                       unsigned short& l) {
    __nv_bfloat16 hb = __float2bfloat16(v);
    float r = v - __bfloat162float(hb);
    __nv_bfloat16 lb = __float2bfloat16(r);
    h = __bfloat16_as_ushort(hb);
    l = __bfloat16_as_ushort(lb);
}
__device__ __forceinline__ void pack2(float f0, float f1,
                                      uint32_t& hi2, uint32_t& lo2) {
    uint32_t h;
    asm("cvt.rn.bf16x2.f32 %0, %1, %2;" : "=r"(h) : "f"(f1), "f"(f0));
    float l0 = f0 - __uint_as_float(h << 16);
    float l1 = f1 - __uint_as_float(h & 0xffff0000u);
    uint32_t l;
    asm("cvt.rn.bf16x2.f32 %0, %1, %2;" : "=r"(l) : "f"(l1), "f"(l0));
    hi2 = h; lo2 = l;
}

// ---------------------------------------------------------------------------
// Input preconvert: gene/expr fp32 -> bf16 hi/lo (once)
// ---------------------------------------------------------------------------
__global__ __launch_bounds__(256) void split_in(
    const float* __restrict__ g, const float* __restrict__ e,
    unsigned short* __restrict__ Gh, unsigned short* __restrict__ Gl,
    unsigned short* __restrict__ Eh, unsigned short* __restrict__ El)
{
    size_t idx = (size_t)blockIdx.x * 256 + threadIdx.x;   // float4 units
    float4 gv = ((const float4*)g)[idx];
    float4 ev = ((const float4*)e)[idx];
    ushort4 h, l;
    bsplit(gv.x, h.x, l.x); bsplit(gv.y, h.y, l.y);
    bsplit(gv.z, h.z, l.z); bsplit(gv.w, h.w, l.w);
    ((ushort4*)Gh)[idx] = h; ((ushort4*)Gl)[idx] = l;
    bsplit(ev.x, h.x, l.x); bsplit(ev.y, h.y, l.y);
    bsplit(ev.z, h.z, l.z); bsplit(ev.w, h.w, l.w);
    ((ushort4*)Eh)[idx] = h; ((ushort4*)El)[idx] = l;
}

// Wf fp32 [1024][512] -> row-major hi/lo (A operand of weight product)
__global__ __launch_bounds__(256) void split_wf(
    const float* __restrict__ Wf,
    unsigned short* __restrict__ Hh, unsigned short* __restrict__ Ll)
{
    size_t idx = (size_t)blockIdx.x * 256 + threadIdx.x;
    float4 v = ((const float4*)Wf)[idx];
    ushort4 h, l;
    bsplit(v.x, h.x, l.x); bsplit(v.y, h.y, l.y);
    bsplit(v.z, h.z, l.z); bsplit(v.w, h.w, l.w);
    ((ushort4*)Hh)[idx] = h; ((ushort4*)Ll)[idx] = l;
}

// ---------------------------------------------------------------------------
// Batched weight preconvert: W[K=512][N=512] -> Wt[N][K] bf16 hi/lo
// planes: 0=Wq 1=Wk 2=Wv 3=Wo
// ---------------------------------------------------------------------------
__global__ void wconv_all(
    const float* __restrict__ Wq, const float* __restrict__ Wk,
    const float* __restrict__ Wv, const float* __restrict__ Wo,
    unsigned short* __restrict__ Wqh, unsigned short* __restrict__ Wql,
    unsigned short* __restrict__ Wkh, unsigned short* __restrict__ Wkl,
    unsigned short* __restrict__ Wvh, unsigned short* __restrict__ Wvl,
    unsigned short* __restrict__ Woh, unsigned short* __restrict__ Wol)
{
    const float* W; unsigned short *Th, *Tl;
    switch (blockIdx.z) {
        case 0:  W = Wq; Th = Wqh; Tl = Wql; break;
        case 1:  W = Wk; Th = Wkh; Tl = Wkl; break;
        case 2:  W = Wv; Th = Wvh; Tl = Wvl; break;
        default: W = Wo; Th = Woh; Tl = Wol; break;
    }
    int k0 = blockIdx.y * 32, n0 = blockIdx.x * 32;
    __shared__ float t[32][33];
    int tx = threadIdx.x, ty = threadIdx.y;
    t[ty][tx] = W[(size_t)(k0 + ty) * D_ + n0 + tx];
    __syncthreads();
    float v = t[tx][ty];
    unsigned short h, l;
    bsplit(v, h, l);
    size_t o = (size_t)(n0 + ty) * D_ + k0 + tx;
    Th[o] = h;
    Tl[o] = l;
}

// folded biases: bfq = (bf@Wq + bq)/8 ; bfk = bf@Wk + bk
__global__ __launch_bounds__(128) void bias_fold(
    const float* __restrict__ bf,
    const float* __restrict__ Wq, const float* __restrict__ Wk,
    const float* __restrict__ bq, const float* __restrict__ bk,
    float* __restrict__ bfq, float* __restrict__ bfk)
{
    int n = blockIdx.x * 128 + threadIdx.x;
    int z = blockIdx.y;
    const float* W  = z ? Wk : Wq;
    const float* b0 = z ? bk : bq;
    float* o = z ? bfk : bfq;
    float s = 0.f;
    for (int k = 0; k < D_; k++) s = fmaf(bf[k], W[(size_t)k * D_ + n], s);
    s += b0[n];
    if (!z) s *= 0.125f;
    o[n] = s;
}

// ---------------------------------------------------------------------------
// 3xBF16 GEMM shared bits. CTA 128x128, K-chunk 32, 8 warps (2x4) of 64x32.
// ---------------------------------------------------------------------------
#define GSTAGE   40960
#define GOFF_AH  0
#define GOFF_AL  10240
#define GOFF_BH  20480
#define GOFF_BL  30720
#define GM_SMEM  (2 * GSTAGE)

__device__ __forceinline__ void gemm_cpPre(uint32_t stage_u32,
                                           uint32_t offH, uint32_t offL,
                                           const unsigned short* Th,
                                           const unsigned short* Tl,
                                           int row0, int K, int k0, int tid)
{
#pragma unroll
    for (int i = 0; i < 2; i++) {
        int fid = tid + i * 256;
        int r = fid >> 2, c16 = fid & 3;
        size_t gs = (size_t)(row0 + r) * K + k0 + c16 * 8;
        CP_ASYNC16(stage_u32 + offH + r * 80 + c16 * 16, (const char*)(Th + gs));
        CP_ASYNC16(stage_u32 + offL + r * 80 + c16 * 16, (const char*)(Tl + gs));
    }
}

__device__ __forceinline__ void gemm_chunk(uint32_t s0, uint32_t arow,
                                           uint32_t brow, float acc[4][4][4])
{
#pragma unroll
    for (int ks = 0; ks < 2; ks++) {
        uint32_t ah[4][4], al[4][4];
#pragma unroll
        for (int mt = 0; mt < 4; mt++) {
            ldm4(s0 + GOFF_AH + arow + mt * 1280 + ks * 32, ah[mt]);
            ldm4(s0 + GOFF_AL + arow + mt * 1280 + ks * 32, al[mt]);
        }
#pragma unroll
        for (int nb = 0; nb < 2; nb++) {
            uint32_t bh4[4], bl4[4];
            ldm4(s0 + GOFF_BH + brow + nb * 1280 + ks * 32, bh4);
            ldm4(s0 + GOFF_BL + brow + nb * 1280 + ks * 32, bl4);
            uint32_t th0[2] = {bh4[0], bh4[2]}, th1[2] = {bh4[1], bh4[3]};
            uint32_t tl0[2] = {bl4[0], bl4[2]}, tl1[2] = {bl4[1], bl4[3]};
#pragma unroll
            for (int mt = 0; mt < 4; mt++) {
                mma_bf16(acc[mt][2 * nb],     ah[mt], th0);
                mma_bf16(acc[mt][2 * nb + 1], ah[mt], th1);
                mma_bf16(acc[mt][2 * nb],     ah[mt], tl0);
                mma_bf16(acc[mt][2 * nb + 1], ah[mt], tl1);
                mma_bf16(acc[mt][2 * nb],     al[mt], th0);
                mma_bf16(acc[mt][2 * nb + 1], al[mt], th1);
            }
        }
    }
}

// shared mainloop (pre-split A, 2 sources split at Ksplit; B [N][K])
__device__ __forceinline__ void gemm_main(
    uint32_t sb, int bm, int bn, int K, int Ksplit,
    const unsigned short* A0h, const unsigned short* A0l, int sA,
    const unsigned short* A1h, const unsigned short* A1l,
    const unsigned short* Bh, const unsigned short* Bl,
    int tid, uint32_t arow, uint32_t brow, float acc[4][4][4])
{
    const int NC = K / 32;
    {
        const unsigned short* Th = (0 < Ksplit) ? A0h : A1h;
        const unsigned short* Tl = (0 < Ksplit) ? A0l : A1l;
        gemm_cpPre(sb, GOFF_AH, GOFF_AL, Th, Tl, bm, sA, 0, tid);
        gemm_cpPre(sb, GOFF_BH, GOFF_BL, Bh, Bl, bn, K, 0, tid);
        CP_COMMIT();
    }
    for (int c = 0; c < NC; c++) {
        const int st = c & 1;
        const bool more = (c + 1 < NC);
        if (more) {
            const int k1 = (c + 1) * 32;
            uint32_t s1 = sb + ((c + 1) & 1) * GSTAGE;
            const unsigned short* Th = (k1 < Ksplit) ? A0h : A1h;
            const unsigned short* Tl = (k1 < Ksplit) ? A0l : A1l;
            const int kc = (k1 < Ksplit) ? k1 : (k1 - Ksplit);
            gemm_cpPre(s1, GOFF_AH, GOFF_AL, Th, Tl, bm, sA, kc, tid);
            gemm_cpPre(s1, GOFF_BH, GOFF_BL, Bh, Bl, bn, K, k1, tid);
            CP_COMMIT();
        }
        if (more) { CP_WAIT1(); } else { CP_WAIT0(); }
        __syncthreads();
        gemm_chunk(sb + st * GSTAGE, arow, brow, acc);
        __syncthreads();
    }
}

// ---------------------------------------------------------------------------
// Out projection: C fp32 row-major = A @ W + bias (A pre-split single source)
// ---------------------------------------------------------------------------
__global__ __launch_bounds__(256, 2) void mm_out(
    const unsigned short* __restrict__ Ahp, const unsigned short* __restrict__ Alp,
    const unsigned short* __restrict__ Bh, const unsigned short* __restrict__ Bl,
    const float* __restrict__ bias, float* __restrict__ C)
{
    extern __shared__ __align__(16) unsigned char smem[];
    const uint32_t sb = smem_u32(smem);
    const int tid = threadIdx.x, lane = tid & 31, wid = tid >> 5;
    const int wy = wid >> 2, wx = wid & 3;
    const int bn = blockIdx.x * 128, bm = blockIdx.y * 128;

    float acc[4][4][4];
#pragma unroll
    for (int i = 0; i < 4; i++)
#pragma unroll
        for (int j = 0; j < 4; j++)
#pragma unroll
            for (int q = 0; q < 4; q++) acc[i][j][q] = 0.f;

    const uint32_t arow = (wy * 64 + (lane & 15)) * 80 + (lane >> 4) * 16;
    const uint32_t brow = (wx * 32 + (lane & 15)) * 80 + (lane >> 4) * 16;

    gemm_main(sb, bm, bn, D_, D_, Ahp, Alp, D_, Ahp, Alp, Bh, Bl,
              tid, arow, brow, acc);

#pragma unroll
    for (int mt = 0; mt < 4; mt++) {
#pragma unroll
        for (int nt = 0; nt < 4; nt++) {
            int r0 = bm + wy * 64 + mt * 16 + (lane >> 2);
            int col = bn + wx * 32 + nt * 8 + 2 * (lane & 3);
            float b0 = bias[col], b1 = bias[col + 1];
            *(float2*)(C + (size_t)r0 * D_ + col) =
                make_float2(acc[mt][nt][0] + b0, acc[mt][nt][1] + b1);
            *(float2*)(C + (size_t)(r0 + 8) * D_ + col) =
                make_float2(acc[mt][nt][2] + b0, acc[mt][nt][3] + b1);
        }
    }
}

// ---------------------------------------------------------------------------
// Weight product: P = Wf[1024,512] @ W{q,k}[512,512], scaled (Q: 1/8),
// output TRANSPOSED + split: P^T [N=512][K=1024] bf16 hi/lo.
// grid (4, 8, 2): z=0 -> Pq (scale 1/8), z=1 -> Pk.
// ---------------------------------------------------------------------------
__global__ __launch_bounds__(256, 2) void wprod(
    const unsigned short* __restrict__ Ah, const unsigned short* __restrict__ Al,
    const unsigned short* __restrict__ Wqh, const unsigned short* __restrict__ Wql,
    const unsigned short* __restrict__ Wkh, const unsigned short* __restrict__ Wkl,
    unsigned short* __restrict__ Pqh, unsigned short* __restrict__ Pql,
    unsigned short* __restrict__ Pkh, unsigned short* __restrict__ Pkl)
{
    extern __shared__ __align__(16) unsigned char smem[];
    const uint32_t sb = smem_u32(smem);
    const int tid = threadIdx.x, lane = tid & 31, wid = tid >> 5;
    const int wy = wid >> 2, wx = wid & 3;
    const int bn = blockIdx.x * 128, bm = blockIdx.y * 128;
    const int z = blockIdx.z;
    const unsigned short* Bh = z ? Wkh : Wqh;
    const unsigned short* Bl = z ? Wkl : Wql;
    unsigned short* Ph = z ? Pkh : Pqh;
    unsigned short* Pl = z ? Pkl : Pql;
    const float sc = z ? 1.0f : 0.125f;

    float acc[4][4][4];
#pragma unroll
    for (int i = 0; i < 4; i++)
#pragma unroll
        for (int j = 0; j < 4; j++)
#pragma unroll
            for (int q = 0; q < 4; q++) acc[i][j][q] = 0.f;

    const uint32_t arow = (wy * 64 + (lane & 15)) * 80 + (lane >> 4) * 16;
    const uint32_t brow = (wx * 32 + (lane & 15)) * 80 + (lane >> 4) * 16;

    gemm_main(sb, bm, bn, D_, D_, Ah, Al, D_, Ah, Al, Bh, Bl,
              tid, arow, brow, acc);

#pragma unroll
    for (int mt = 0; mt < 4; mt++) {
#pragma unroll
        for (int nt = 0; nt < 4; nt++) {
            int r0 = bm + wy * 64 + mt * 16 + (lane >> 2);
            int col = bn + wx * 32 + nt * 8 + 2 * (lane & 3);
            unsigned short h, l;
            bsplit(acc[mt][nt][0] * sc, h, l);
            Ph[(size_t)col * (2 * D_) + r0] = h;
            Pl[(size_t)col * (2 * D_) + r0] = l;
            bsplit(acc[mt][nt][1] * sc, h, l);
            Ph[(size_t)(col + 1) * (2 * D_) + r0] = h;
            Pl[(size_t)(col + 1) * (2 * D_) + r0] = l;
            bsplit(acc[mt][nt][2] * sc, h, l);
            Ph[(size_t)col * (2 * D_) + r0 + 8] = h;
            Pl[(size_t)col * (2 * D_) + r0 + 8] = l;
            bsplit(acc[mt][nt][3] * sc, h, l);
            Ph[(size_t)(col + 1) * (2 * D_) + r0 + 8] = h;
            Pl[(size_t)(col + 1) * (2 * D_) + r0 + 8] = l;
        }
    }
}

// ---------------------------------------------------------------------------
// Q/K/V projection (fused stage folded away):
//   z=0: Q = X @ Pq + bfq   (K=1024, X = [gene||expr], pre-scaled 1/8)
//   z=1: K = X @ Pk + bfk   (K=1024)
//   z=2: V = expr @ Wv + bv (K=512)
// Output head-split bf16 hi/lo [B,H,S,HD].
// ---------------------------------------------------------------------------
__global__ __launch_bounds__(256, 2) void mm_qkv2(
    const unsigned short* __restrict__ Gh, const unsigned short* __restrict__ Gl,
    const unsigned short* __restrict__ Eh, const unsigned short* __restrict__ El,
    const unsigned short* __restrict__ Pqh, const unsigned short* __restrict__ Pql,
    const unsigned short* __restrict__ Pkh, const unsigned short* __restrict__ Pkl,
    const unsigned short* __restrict__ Wvh, const unsigned short* __restrict__ Wvl,
    const float* __restrict__ bfq, const float* __restrict__ bfk,
    const float* __restrict__ bv,
    unsigned short* __restrict__ Qh, unsigned short* __restrict__ Ql,
    unsigned short* __restrict__ Kh, unsigned short* __restrict__ Kl,
    unsigned short* __restrict__ Vh, unsigned short* __restrict__ Vl)
{
    extern __shared__ __align__(16) unsigned char smem[];
    const uint32_t sb = smem_u32(smem);
    const int tid = threadIdx.x, lane = tid & 31, wid = tid >> 5;
    const int wy = wid >> 2, wx = wid & 3;
    const int bn = blockIdx.x * 128, bm = blockIdx.y * 128;
    const int z = blockIdx.z;

    const unsigned short* A0h = (z == 2) ? Eh : Gh;
    const unsigned short* A0l = (z == 2) ? El : Gl;
    const unsigned short* Bh = (z == 0) ? Pqh : (z == 1) ? Pkh : Wvh;
    const unsigned short* Bl = (z == 0) ? Pql : (z == 1) ? Pkl : Wvl;
    const float* bias = (z == 0) ? bfq : (z == 1) ? bfk : bv;
    unsigned short* Ch = (z == 0) ? Qh : (z == 1) ? Kh : Vh;
    unsigned short* Cl = (z == 0) ? Ql : (z == 1) ? Kl : Vl;
    const int K = (z == 2) ? D_ : 2 * D_;

    float acc[4][4][4];
#pragma unroll
    for (int i = 0; i < 4; i++)
#pragma unroll
        for (int j = 0; j < 4; j++)
#pragma unroll
            for (int q = 0; q < 4; q++) acc[i][j][q] = 0.f;

    const uint32_t arow = (wy * 64 + (lane & 15)) * 80 + (lane >> 4) * 16;
    const uint32_t brow = (wx * 32 + (lane & 15)) * 80 + (lane >> 4) * 16;

    gemm_main(sb, bm, bn, K, D_, A0h, A0l, D_, Eh, El, Bh, Bl,
              tid, arow, brow, acc);

#pragma unroll
    for (int mt = 0; mt < 4; mt++) {
#pragma unroll
        for (int nt = 0; nt < 4; nt++) {
            int r0 = bm + wy * 64 + mt * 16 + (lane >> 2);
            int col = bn + wx * 32 + nt * 8 + 2 * (lane & 3);
            float b0 = bias[col], b1 = bias[col + 1];
            float2 v0 = make_float2(acc[mt][nt][0] + b0, acc[mt][nt][1] + b1);
            float2 v1 = make_float2(acc[mt][nt][2] + b0, acc[mt][nt][3] + b1);
            int hh = col >> 6, dd = col & (HD_ - 1);
            int bb0 = r0 >> 11, ss0 = r0 & (S_ - 1);
            size_t o0 = (((size_t)bb0 * H_ + hh) * S_ + ss0) * HD_ + dd;
            unsigned short hx, lx, hy, ly;
            bsplit(v0.x, hx, lx); bsplit(v0.y, hy, ly);
            *(ushort2*)(Ch + o0) = make_ushort2(hx, hy);
            *(ushort2*)(Cl + o0) = make_ushort2(lx, ly);
            int r1 = r0 + 8;
            int bb1 = r1 >> 11, ss1 = r1 & (S_ - 1);
            size_t o1 = (((size_t)bb1 * H_ + hh) * S_ + ss1) * HD_ + dd;
            bsplit(v1.x, hx, lx); bsplit(v1.y, hy, ly);
            *(ushort2*)(Ch + o1) = make_ushort2(hx, hy);
            *(ushort2*)(Cl + o1) = make_ushort2(lx, ly);
        }
    }
}

// ---------------------------------------------------------------------------
// Flash attention (R11/R15 structure — best measured). Unchanged.
// ---------------------------------------------------------------------------
#define AQ_H 0
#define AQ_L 18432
#define ASTG_BASE 36864
#define AS_KH 0
#define AS_KL 9216
#define AS_VH 18432
#define AS_VL 27648
#define AS_M  36864
#define MPITCH 304
#define ASTG  (36864 + 128 * MPITCH)        // 75776
#define ATTN_SMEM (36864 + 2 * ASTG)        // 188416

__device__ __forceinline__ void attn_cp_stage(
    uint32_t sb, int s,
    const unsigned short* Kh, const unsigned short* Kl,
    const unsigned short* Vh, const unsigned short* Vl,
    const float* Mp, size_t bhS, int q0, int kk0, int tid)
{
    const uint32_t base = sb + ASTG_BASE + s * ASTG;
#pragma unroll
    for (int i = 0; i < 8; i++) {
        const int t = i >> 1;
        const int idx = tid + (i & 1) * 256;
        const int row = idx >> 3, c16 = idx & 7;
        const unsigned short* sp = (t == 0) ? Kh : (t == 1) ? Kl
                                 : (t == 2) ? Vh : Vl;
        CP_ASYNC16(base + t * 9216 + row * 144 + c16 * 16,
                   (const char*)(sp + (bhS + kk0 + row) * HD_ + c16 * 8));
    }
#pragma unroll
    for (int i = 0; i < 8; i++) {
        const int idx = tid + i * 256;
        const int row = idx >> 4, c16 = idx & 15;
        CP_ASYNC16(base + AS_M + row * MPITCH + c16 * 16,
                   (const char*)(Mp + (size_t)(q0 + row) * S_ + kk0 + c16 * 4));
    }
}

__global__ __launch_bounds__(256, 1) void attn_mma(
    const unsigned short* __restrict__ Qh, const unsigned short* __restrict__ Ql,
    const unsigned short* __restrict__ Kh, const unsigned short* __restrict__ Kl,
    const unsigned short* __restrict__ Vh, const unsigned short* __restrict__ Vl,
    const float* __restrict__ Mm,
    unsigned short* __restrict__ Oh, unsigned short* __restrict__ Ol)
{
    extern __shared__ __align__(16) unsigned char smem[];
    const uint32_t sb = smem_u32(smem);

    const int q0 = blockIdx.x * 128;
    const int h  = blockIdx.y;
    const int b  = blockIdx.z;
    const int tid = threadIdx.x, lane = tid & 31, w = tid >> 5;
    const int qr = lane >> 2, qc = lane & 3;

    const size_t bhS = ((size_t)b * H_ + h) * S_;
    const float* Mp = Mm + (size_t)b * S_ * S_;

#pragma unroll
    for (int i = 0; i < 8; i++) {
        const int idx = tid + (i & 3) * 256;
        const int row = idx >> 3, c16 = idx & 7;
        const unsigned short* sp = (i < 4) ? Qh : Ql;
        const uint32_t off = (i < 4) ? AQ_H : AQ_L;
        CP_ASYNC16(sb + off + row * 144 + c16 * 16,
                   (const char*)(sp + (bhS + q0 + row) * HD_ + c16 * 8));
    }
    attn_cp_stage(sb, 0, Kh, Kl, Vh, Vl, Mp, bhS, q0, 0, tid);
    CP_COMMIT();

    float O[8][4];
#pragma unroll
    for (int t = 0; t < 8; t++)
#pragma unroll
        for (int j = 0; j < 4; j++) O[t][j] = 0.f;
    float m0 = -1e30f, m1 = -1e30f, Z0 = 0.f, Z1 = 0.f, T0 = 0.f, T1 = 0.f;

    const uint32_t qrow = (w * 16 + (lane & 15)) * 144 + (lane >> 4) * 16;
    const uint32_t klrow = (lane & 15) * 144 + (lane >> 4) * 16;

    uint32_t qah[4][4], qal[4][4];

    const int NB = S_ / 64;
    for (int kb = 0; kb < NB; kb++) {
        const int st = kb & 1;
        const bool more = (kb + 1 < NB);
        if (more) {
            attn_cp_stage(sb, st ^ 1, Kh, Kl, Vh, Vl, Mp, bhS, q0,
                          (kb + 1) * 64, tid);
            CP_COMMIT();
            CP_WAIT1();
        } else {
            CP_WAIT0();
        }
        __syncthreads();

        if (kb == 0) {
#pragma unroll
            for (int ks = 0; ks < 4; ks++) {
                ldm4(sb + AQ_H + qrow + ks * 32, qah[ks]);
                ldm4(sb + AQ_L + qrow + ks * 32, qal[ks]);
            }
        }

        const uint32_t stg = sb + ASTG_BASE + st * ASTG;

        float S[8][4];
#pragma unroll
        for (int t = 0; t < 8; t++)
#pragma unroll
            for (int j = 0; j < 4; j++) S[t][j] = 0.f;
#pragma unroll
        for (int ks = 0; ks < 4; ks++) {
#pragma unroll
            for (int nb = 0; nb < 4; nb++) {
                uint32_t bh4[4], bl4[4];
                ldm4(stg + AS_KH + klrow + nb * 2304 + ks * 32, bh4);
                ldm4(stg + AS_KL + klrow + nb * 2304 + ks * 32, bl4);
                uint32_t th0[2] = {bh4[0], bh4[2]}, th1[2] = {bh4[1], bh4[3]};
                uint32_t tl0[2] = {bl4[0], bl4[2]}, tl1[2] = {bl4[1], bl4[3]};
                mma_bf16(S[2 * nb],     qah[ks], th0);
                mma_bf16(S[2 * nb + 1], qah[ks], th1);
                mma_bf16(S[2 * nb],     qah[ks], tl0);
                mma_bf16(S[2 * nb + 1], qah[ks], tl1);
                mma_bf16(S[2 * nb],     qal[ks], th0);
                mma_bf16(S[2 * nb + 1], qal[ks], th1);
            }
        }

        const unsigned char* msp = smem + ASTG_BASE + st * ASTG + AS_M;
        const int mr0 = (w * 16 + qr) * MPITCH + qc * 8;
        float bm0 = -1e30f, bm1 = -1e30f;
        float mva[8], mvb[8], mvc[8], mvd[8];
#pragma unroll
        for (int t = 0; t < 8; t++) {
            float2 ma = *(const float2*)(msp + mr0 + t * 32);
            float2 mb = *(const float2*)(msp + mr0 + 8 * MPITCH + t * 32);
            mva[t] = ma.x; mvb[t] = ma.y; mvc[t] = mb.x; mvd[t] = mb.y;
            S[t][0] *= ma.x;
            S[t][1] *= ma.y;
            S[t][2] *= mb.x;
            S[t][3] *= mb.y;
            bm0 = fmaxf(bm0, fmaxf(S[t][0], S[t][1]));
            bm1 = fmaxf(bm1, fmaxf(S[t][2], S[t][3]));
        }
        bm0 = fmaxf(bm0, __shfl_xor_sync(0xffffffffu, bm0, 1));
        bm0 = fmaxf(bm0, __shfl_xor_sync(0xffffffffu, bm0, 2));
        bm1 = fmaxf(bm1, __shfl_xor_sync(0xffffffffu, bm1, 1));
        bm1 = fmaxf(bm1, __shfl_xor_sync(0xffffffffu, bm1, 2));
        if (bm0 > m0) {
            float f0 = __expf(m0 - bm0);
            m0 = bm0; Z0 *= f0; T0 *= f0;
#pragma unroll
            for (int t = 0; t < 8; t++) { O[t][0] *= f0; O[t][1] *= f0; }
        }
        if (bm1 > m1) {
            float f1 = __expf(m1 - bm1);
            m1 = bm1; Z1 *= f1; T1 *= f1;
#pragma unroll
            for (int t = 0; t < 8; t++) { O[t][2] *= f1; O[t][3] *= f1; }
        }
#pragma unroll
        for (int t = 0; t < 8; t++) {
            float e0 = __expf(S[t][0] - m0);
            float e1 = __expf(S[t][1] - m0);
            float e2 = __expf(S[t][2] - m1);
            float e3 = __expf(S[t][3] - m1);
            Z0 += e0 + e1; Z1 += e2 + e3;
            float p0 = e0 * mva[t], p1 = e1 * mvb[t];
            float p2 = e2 * mvc[t], p3 = e3 * mvd[t];
            T0 += p0 + p1; T1 += p2 + p3;
            S[t][0] = p0; S[t][1] = p1; S[t][2] = p2; S[t][3] = p3;
        }

        uint32_t phi[4][4], plo[4][4];
#pragma unroll
        for (int kt = 0; kt < 4; kt++) {
            pack2(S[2 * kt][0],     S[2 * kt][1],     phi[kt][0], plo[kt][0]);
            pack2(S[2 * kt][2],     S[2 * kt][3],     phi[kt][1], plo[kt][1]);
            pack2(S[2 * kt + 1][0], S[2 * kt + 1][1], phi[kt][2], plo[kt][2]);
            pack2(S[2 * kt + 1][2], S[2 * kt + 1][3], phi[kt][3], plo[kt][3]);
        }

#pragma unroll
        for (int kt = 0; kt < 4; kt++) {
#pragma unroll
            for (int nb = 0; nb < 4; nb++) {
                uint32_t vh4[4], vl4[4];
                ldm4t(stg + AS_VH + kt * 2304 + klrow + nb * 32, vh4);
                ldm4t(stg + AS_VL + kt * 2304 + klrow + nb * 32, vl4);
                uint32_t th0[2] = {vh4[0], vh4[1]}, th1[2] = {vh4[2], vh4[3]};
                uint32_t tl0[2] = {vl4[0], vl4[1]}, tl1[2] = {vl4[2], vl4[3]};
                mma_bf16(O[2 * nb],     phi[kt], th0);
                mma_bf16(O[2 * nb + 1], phi[kt], th1);
                mma_bf16(O[2 * nb],     phi[kt], tl0);
                mma_bf16(O[2 * nb + 1], phi[kt], tl1);
                mma_bf16(O[2 * nb],     plo[kt], th0);
                mma_bf16(O[2 * nb + 1], plo[kt], th1);
            }
        }
        __syncthreads();
    }

    T0 += __shfl_xor_sync(0xffffffffu, T0, 1);
    T0 += __shfl_xor_sync(0xffffffffu, T0, 2);
    T1 += __shfl_xor_sync(0xffffffffu, T1, 1);
    T1 += __shfl_xor_sync(0xffffffffu, T1, 2);
    Z0 += __shfl_xor_sync(0xffffffffu, Z0, 1);
    Z0 += __shfl_xor_sync(0xffffffffu, Z0, 2);
    Z1 += __shfl_xor_sync(0xffffffffu, Z1, 1);
    Z1 += __shfl_xor_sync(0xffffffffu, Z1, 2);
    float inv0 = 1.0f / (T0 + EPS_ * Z0);
    float inv1 = 1.0f / (T1 + EPS_ * Z1);

    int gr0 = q0 + w * 16 + qr;
#pragma unroll
    for (int t = 0; t < 8; t++) {
        int d = t * 8 + 2 * qc;
        size_t o0 = ((size_t)b * S_ + gr0) * D_ + h * HD_ + d;
        size_t o1 = ((size_t)b * S_ + gr0 + 8) * D_ + h * HD_ + d;
        uint32_t h2, l2;
        pack2(O[t][0] * inv0, O[t][1] * inv0, h2, l2);
        *(uint32_t*)(Oh + o0) = h2;
        *(uint32_t*)(Ol + o0) = l2;
        pack2(O[t][2] * inv1, O[t][3] * inv1, h2, l2);
        *(uint32_t*)(Oh + o1) = h2;
        *(uint32_t*)(Ol + o1) = l2;
    }
}

// ---------------------------------------------------------------------------
// Host
// ---------------------------------------------------------------------------
extern "C" void kernel_launch(void* const* d_in, const int* in_sizes, int n_in,
                              void* d_out, int out_size)
{
    const float* gene = (const float*)d_in[0];
    const float* expr = (const float*)d_in[1];
    const float* Mm   = (const float*)d_in[2];
    const float* Wf   = (const float*)d_in[3];
    const float* bf   = (const float*)d_in[4];
    const float* Wq   = (const float*)d_in[5];
    const float* bq   = (const float*)d_in[6];
    const float* Wk   = (const float*)d_in[7];
    const float* bk   = (const float*)d_in[8];
    const float* Wv   = (const float*)d_in[9];
    const float* bv   = (const float*)d_in[10];
    const float* Wo   = (const float*)d_in[11];
    const float* bo   = (const float*)d_in[12];
    float* out = (float*)d_out;

    unsigned short *Gh, *Gl, *Eh, *El, *Qh, *Ql, *Kh, *Kl, *Vh, *Vl;
    unsigned short *Ahb, *Alb, *Wfh, *Wfl;
    unsigned short *Wqh, *Wql, *Wkh, *Wkl, *Wvh, *Wvl, *Woh, *Wol;
    unsigned short *Pqh, *Pql, *Pkh, *Pkl;
    float *bfq, *bfk;
    cudaGetSymbolAddress((void**)&Gh,  g_Gh);
    cudaGetSymbolAddress((void**)&Gl,  g_Gl);
    cudaGetSymbolAddress((void**)&Eh,  g_Eh);
    cudaGetSymbolAddress((void**)&El,  g_El);
    cudaGetSymbolAddress((void**)&Qh,  g_Qh);
    cudaGetSymbolAddress((void**)&Ql,  g_Ql);
    cudaGetSymbolAddress((void**)&Kh,  g_Kh);
    cudaGetSymbolAddress((void**)&Kl,  g_Kl);
    cudaGetSymbolAddress((void**)&Vh,  g_Vh);
    cudaGetSymbolAddress((void**)&Vl,  g_Vl);
    cudaGetSymbolAddress((void**)&Ahb, g_Ah);
    cudaGetSymbolAddress((void**)&Alb, g_Al);
    cudaGetSymbolAddress((void**)&Wfh, g_Wfrm_h);
    cudaGetSymbolAddress((void**)&Wfl, g_Wfrm_l);
    cudaGetSymbolAddress((void**)&Wqh, g_Wq_h);
    cudaGetSymbolAddress((void**)&Wql, g_Wq_l);
    cudaGetSymbolAddress((void**)&Wkh, g_Wk_h);
    cudaGetSymbolAddress((void**)&Wkl, g_Wk_l);
    cudaGetSymbolAddress((void**)&Wvh, g_Wv_h);
    cudaGetSymbolAddress((void**)&Wvl, g_Wv_l);
    cudaGetSymbolAddress((void**)&Woh, g_Wo_h);
    cudaGetSymbolAddress((void**)&Wol, g_Wo_l);
    cudaGetSymbolAddress((void**)&Pqh, g_Pq_h);
    cudaGetSymbolAddress((void**)&Pql, g_Pq_l);
    cudaGetSymbolAddress((void**)&Pkh, g_Pk_h);
    cudaGetSymbolAddress((void**)&Pkl, g_Pk_l);
    cudaGetSymbolAddress((void**)&bfq, g_bfq);
    cudaGetSymbolAddress((void**)&bfk, g_bfk);

    cudaFuncSetAttribute(wprod,   cudaFuncAttributeMaxDynamicSharedMemorySize, GM_SMEM);
    cudaFuncSetAttribute(mm_qkv2, cudaFuncAttributeMaxDynamicSharedMemorySize, GM_SMEM);
    cudaFuncSetAttribute(mm_out,  cudaFuncAttributeMaxDynamicSharedMemorySize, GM_SMEM);
    cudaFuncSetAttribute(attn_mma, cudaFuncAttributeMaxDynamicSharedMemorySize, ATTN_SMEM);

    // 1) preconversions (independent)
    split_in<<<ROWS_ * D_ / 4 / 256, 256>>>(gene, expr, Gh, Gl, Eh, El);
    split_wf<<<(2 * D_) * D_ / 4 / 256, 256>>>(Wf, Wfh, Wfl);
    wconv_all<<<dim3(16, 16, 4), dim3(32, 32)>>>(
        Wq, Wk, Wv, Wo,
        Wqh, Wql, Wkh, Wkl, Wvh, Wvl, Woh, Wol);
    bias_fold<<<dim3(4, 2), 128>>>(bf, Wq, Wk, bq, bk, bfq, bfk);

    // 2) weight products Pq = (Wf@Wq)/8, Pk = Wf@Wk  (transposed hi/lo)
    wprod<<<dim3(4, 8, 2), 256, GM_SMEM>>>(Wfh, Wfl, Wqh, Wql, Wkh, Wkl,
                                           Pqh, Pql, Pkh, Pkl);

    // 3) Q, K (K=1024, fused folded) and V (K=512) in ONE launch
    mm_qkv2<<<dim3(4, 64, 3), 256, GM_SMEM>>>(Gh, Gl, Eh, El,
                                              Pqh, Pql, Pkh, Pkl, Wvh, Wvl,
                                              bfq, bfk, bv,
                                              Qh, Ql, Kh, Kl, Vh, Vl);

    // 4) flash attention (unchanged), bf16 hi/lo output
    attn_mma<<<dim3(S_ / 128, H_, B_), 256, ATTN_SMEM>>>(Qh, Ql, Kh, Kl,
                                                         Vh, Vl, Mm,
                                                         Ahb, Alb);

    // 5) out = attn @ Wo + bo
    mm_out<<<dim3(D_ / 128, ROWS_ / 128), 256, GM_SMEM>>>(Ahb, Alb, Woh, Wol,
                                                          bo, out);
}

// round 17
// speedup vs baseline: 1.0248x; 1.0248x over previous
#include <cuda_runtime.h>
#include <cuda_bf16.h>
#include <stdint.h>

#define B_   4
#define S_   2048
#define D_   512
#define H_   8
#define HD_  64
#define ROWS_ (B_ * S_)          // 8192
#define EPS_ 1e-8f

// ---------------------------------------------------------------------------
// Scratch (__device__ globals; allocations are forbidden)
// ---------------------------------------------------------------------------
__device__ unsigned short g_Gh[(size_t)ROWS_ * D_];
__device__ unsigned short g_Gl[(size_t)ROWS_ * D_];
__device__ unsigned short g_Eh[(size_t)ROWS_ * D_];
__device__ unsigned short g_El[(size_t)ROWS_ * D_];
__device__ unsigned short g_Qh[(size_t)ROWS_ * D_];
__device__ unsigned short g_Ql[(size_t)ROWS_ * D_];
__device__ unsigned short g_Kh[(size_t)ROWS_ * D_];
__device__ unsigned short g_Kl[(size_t)ROWS_ * D_];
__device__ unsigned short g_Vh[(size_t)ROWS_ * D_];
__device__ unsigned short g_Vl[(size_t)ROWS_ * D_];
__device__ unsigned short g_Ah[(size_t)ROWS_ * D_];
__device__ unsigned short g_Al[(size_t)ROWS_ * D_];
// Wf split row-major [1024][512] (A operand of weight products)
__device__ unsigned short g_Wfrm_h[(size_t)(2 * D_) * D_];
__device__ unsigned short g_Wfrm_l[(size_t)(2 * D_) * D_];
// weight [N][K] hi/lo splits
__device__ unsigned short g_Wq_h[(size_t)D_ * D_];
__device__ unsigned short g_Wq_l[(size_t)D_ * D_];
__device__ unsigned short g_Wk_h[(size_t)D_ * D_];
__device__ unsigned short g_Wk_l[(size_t)D_ * D_];
__device__ unsigned short g_Wv_h[(size_t)D_ * D_];
__device__ unsigned short g_Wv_l[(size_t)D_ * D_];
__device__ unsigned short g_Wo_h[(size_t)D_ * D_];
__device__ unsigned short g_Wo_l[(size_t)D_ * D_];
// folded weight products (Wf@Wq)*(1/8), Wf@Wk as [N=512][K=1024] hi/lo
__device__ unsigned short g_Pq_h[(size_t)D_ * 2 * D_];
__device__ unsigned short g_Pq_l[(size_t)D_ * 2 * D_];
__device__ unsigned short g_Pk_h[(size_t)D_ * 2 * D_];
__device__ unsigned short g_Pk_l[(size_t)D_ * 2 * D_];
// folded biases
__device__ float g_bfq[D_];
__device__ float g_bfk[D_];

// ---------------------------------------------------------------------------
// sm_80-level PTX helpers (NO tcgen05 — build target is plain sm_103)
// ---------------------------------------------------------------------------
__device__ __forceinline__ uint32_t smem_u32(const void* p) {
    uint32_t a;
    asm("{ .reg .u64 t; cvta.to.shared.u64 t, %1; cvt.u32.u64 %0, t; }"
        : "=r"(a) : "l"(p));
    return a;
}
__device__ __forceinline__ void ldm4(uint32_t addr, uint32_t* r) {
    asm volatile("ldmatrix.sync.aligned.m8n8.x4.shared.b16 {%0,%1,%2,%3}, [%4];"
                 : "=r"(r[0]), "=r"(r[1]), "=r"(r[2]), "=r"(r[3]) : "r"(addr));
}
__device__ __forceinline__ void ldm4t(uint32_t addr, uint32_t* r) {
    asm volatile("ldmatrix.sync.aligned.m8n8.x4.trans.shared.b16 {%0,%1,%2,%3}, [%4];"
                 : "=r"(r[0]), "=r"(r[1]), "=r"(r[2]), "=r"(r[3]) : "r"(addr));
}
__device__ __forceinline__ void mma_bf16(float* c, const uint32_t* a,
                                         const uint32_t* b) {
    asm volatile("mma.sync.aligned.m16n8k16.row.col.f32.bf16.bf16.f32 "
                 "{%0,%1,%2,%3}, {%4,%5,%6,%7}, {%8,%9}, {%0,%1,%2,%3};"
                 : "+f"(c[0]), "+f"(c[1]), "+f"(c[2]), "+f"(c[3])
                 : "r"(a[0]), "r"(a[1]), "r"(a[2]), "r"(a[3]),
                   "r"(b[0]), "r"(b[1]));
}
#define CP_ASYNC16(dst, src) \
    asm volatile("cp.async.ca.shared.global [%0], [%1], 16;" \
                 :: "r"(dst), "l"(src))
#define CP_COMMIT() asm volatile("cp.async.commit_group;" ::: "memory")
#define CP_WAIT0()  asm volatile("cp.async.wait_group 0;" ::: "memory")
#define CP_WAIT1()  asm volatile("cp.async.wait_group 1;" ::: "memory")

__device__ __forceinline__ void bsplit(float v, unsigned short& h,
                                       unsigned short& l) {
    __nv_bfloat16 hb = __float2bfloat16(v);
    float r = v - __bfloat162float(hb);
    __nv_bfloat16 lb = __float2bfloat16(r);
    h = __bfloat16_as_ushort(hb);
    l = __bfloat16_as_ushort(lb);
}
__device__ __forceinline__ void pack2(float f0, float f1,
                                      uint32_t& hi2, uint32_t& lo2) {
    uint32_t h;
    asm("cvt.rn.bf16x2.f32 %0, %1, %2;" : "=r"(h) : "f"(f1), "f"(f0));
    float l0 = f0 - __uint_as_float(h << 16);
    float l1 = f1 - __uint_as_float(h & 0xffff0000u);
    uint32_t l;
    asm("cvt.rn.bf16x2.f32 %0, %1, %2;" : "=r"(l) : "f"(l1), "f"(l0));
    hi2 = h; lo2 = l;
}

// ---------------------------------------------------------------------------
// Input preconvert: gene/expr fp32 -> bf16 hi/lo (once)
// ---------------------------------------------------------------------------
__global__ __launch_bounds__(256) void split_in(
    const float* __restrict__ g, const float* __restrict__ e,
    unsigned short* __restrict__ Gh, unsigned short* __restrict__ Gl,
    unsigned short* __restrict__ Eh, unsigned short* __restrict__ El)
{
    size_t idx = (size_t)blockIdx.x * 256 + threadIdx.x;   // float4 units
    float4 gv = ((const float4*)g)[idx];
    float4 ev = ((const float4*)e)[idx];
    ushort4 h, l;
    bsplit(gv.x, h.x, l.x); bsplit(gv.y, h.y, l.y);
    bsplit(gv.z, h.z, l.z); bsplit(gv.w, h.w, l.w);
    ((ushort4*)Gh)[idx] = h; ((ushort4*)Gl)[idx] = l;
    bsplit(ev.x, h.x, l.x); bsplit(ev.y, h.y, l.y);
    bsplit(ev.z, h.z, l.z); bsplit(ev.w, h.w, l.w);
    ((ushort4*)Eh)[idx] = h; ((ushort4*)El)[idx] = l;
}

// Wf fp32 [1024][512] -> row-major hi/lo (A operand of weight product)
__global__ __launch_bounds__(256) void split_wf(
    const float* __restrict__ Wf,
    unsigned short* __restrict__ Hh, unsigned short* __restrict__ Ll)
{
    size_t idx = (size_t)blockIdx.x * 256 + threadIdx.x;
    float4 v = ((const float4*)Wf)[idx];
    ushort4 h, l;
    bsplit(v.x, h.x, l.x); bsplit(v.y, h.y, l.y);
    bsplit(v.z, h.z, l.z); bsplit(v.w, h.w, l.w);
    ((ushort4*)Hh)[idx] = h; ((ushort4*)Ll)[idx] = l;
}

// ---------------------------------------------------------------------------
// Batched weight preconvert: W[K=512][N=512] -> Wt[N][K] bf16 hi/lo
// planes: 0=Wq 1=Wk 2=Wv 3=Wo
// ---------------------------------------------------------------------------
__global__ void wconv_all(
    const float* __restrict__ Wq, const float* __restrict__ Wk,
    const float* __restrict__ Wv, const float* __restrict__ Wo,
    unsigned short* __restrict__ Wqh, unsigned short* __restrict__ Wql,
    unsigned short* __restrict__ Wkh, unsigned short* __restrict__ Wkl,
    unsigned short* __restrict__ Wvh, unsigned short* __restrict__ Wvl,
    unsigned short* __restrict__ Woh, unsigned short* __restrict__ Wol)
{
    const float* W; unsigned short *Th, *Tl;
    switch (blockIdx.z) {
        case 0:  W = Wq; Th = Wqh; Tl = Wql; break;
        case 1:  W = Wk; Th = Wkh; Tl = Wkl; break;
        case 2:  W = Wv; Th = Wvh; Tl = Wvl; break;
        default: W = Wo; Th = Woh; Tl = Wol; break;
    }
    int k0 = blockIdx.y * 32, n0 = blockIdx.x * 32;
    __shared__ float t[32][33];
    int tx = threadIdx.x, ty = threadIdx.y;
    t[ty][tx] = W[(size_t)(k0 + ty) * D_ + n0 + tx];
    __syncthreads();
    float v = t[tx][ty];
    unsigned short h, l;
    bsplit(v, h, l);
    size_t o = (size_t)(n0 + ty) * D_ + k0 + tx;
    Th[o] = h;
    Tl[o] = l;
}

// folded biases (warp-per-output): bfq = (bf@Wq + bq)/8 ; bfk = bf@Wk + bk
// grid (64, 2) x 256 threads = 128 warps; warp w of block x computes n = x*8+w.
__global__ __launch_bounds__(256) void bias_fold(
    const float* __restrict__ bf,
    const float* __restrict__ Wq, const float* __restrict__ Wk,
    const float* __restrict__ bq, const float* __restrict__ bk,
    float* __restrict__ bfq, float* __restrict__ bfk)
{
    const int lane = threadIdx.x & 31, wrp = threadIdx.x >> 5;
    const int n = blockIdx.x * 8 + wrp;
    const int z = blockIdx.y;
    const float* W = z ? Wk : Wq;
    float s = 0.f;
#pragma unroll
    for (int k = lane; k < D_; k += 32)
        s = fmaf(bf[k], W[(size_t)k * D_ + n], s);
#pragma unroll
    for (int o = 16; o; o >>= 1)
        s += __shfl_xor_sync(0xffffffffu, s, o);
    if (lane == 0) {
        s += (z ? bk : bq)[n];
        if (!z) s *= 0.125f;
        (z ? bfk : bfq)[n] = s;
    }
}

// ---------------------------------------------------------------------------
// 3xBF16 GEMM shared bits. CTA 128x128, K-chunk 32, 8 warps (2x4) of 64x32.
// ---------------------------------------------------------------------------
#define GSTAGE   40960
#define GOFF_AH  0
#define GOFF_AL  10240
#define GOFF_BH  20480
#define GOFF_BL  30720
#define GM_SMEM  (2 * GSTAGE)

__device__ __forceinline__ void gemm_cpPre(uint32_t stage_u32,
                                           uint32_t offH, uint32_t offL,
                                           const unsigned short* Th,
                                           const unsigned short* Tl,
                                           int row0, int K, int k0, int tid)
{
#pragma unroll
    for (int i = 0; i < 2; i++) {
        int fid = tid + i * 256;
        int r = fid >> 2, c16 = fid & 3;
        size_t gs = (size_t)(row0 + r) * K + k0 + c16 * 8;
        CP_ASYNC16(stage_u32 + offH + r * 80 + c16 * 16, (const char*)(Th + gs));
        CP_ASYNC16(stage_u32 + offL + r * 80 + c16 * 16, (const char*)(Tl + gs));
    }
}

__device__ __forceinline__ void gemm_chunk(uint32_t s0, uint32_t arow,
                                           uint32_t brow, float acc[4][4][4])
{
#pragma unroll
    for (int ks = 0; ks < 2; ks++) {
        uint32_t ah[4][4], al[4][4];
#pragma unroll
        for (int mt = 0; mt < 4; mt++) {
            ldm4(s0 + GOFF_AH + arow + mt * 1280 + ks * 32, ah[mt]);
            ldm4(s0 + GOFF_AL + arow + mt * 1280 + ks * 32, al[mt]);
        }
#pragma unroll
        for (int nb = 0; nb < 2; nb++) {
            uint32_t bh4[4], bl4[4];
            ldm4(s0 + GOFF_BH + brow + nb * 1280 + ks * 32, bh4);
            ldm4(s0 + GOFF_BL + brow + nb * 1280 + ks * 32, bl4);
            uint32_t th0[2] = {bh4[0], bh4[2]}, th1[2] = {bh4[1], bh4[3]};
            uint32_t tl0[2] = {bl4[0], bl4[2]}, tl1[2] = {bl4[1], bl4[3]};
#pragma unroll
            for (int mt = 0; mt < 4; mt++) {
                mma_bf16(acc[mt][2 * nb],     ah[mt], th0);
                mma_bf16(acc[mt][2 * nb + 1], ah[mt], th1);
                mma_bf16(acc[mt][2 * nb],     ah[mt], tl0);
                mma_bf16(acc[mt][2 * nb + 1], ah[mt], tl1);
                mma_bf16(acc[mt][2 * nb],     al[mt], th0);
                mma_bf16(acc[mt][2 * nb + 1], al[mt], th1);
            }
        }
    }
}

// shared mainloop (pre-split A, 2 sources split at Ksplit; B [N][K])
__device__ __forceinline__ void gemm_main(
    uint32_t sb, int bm, int bn, int K, int Ksplit,
    const unsigned short* A0h, const unsigned short* A0l, int sA,
    const unsigned short* A1h, const unsigned short* A1l,
    const unsigned short* Bh, const unsigned short* Bl,
    int tid, uint32_t arow, uint32_t brow, float acc[4][4][4])
{
    const int NC = K / 32;
    {
        const unsigned short* Th = (0 < Ksplit) ? A0h : A1h;
        const unsigned short* Tl = (0 < Ksplit) ? A0l : A1l;
        gemm_cpPre(sb, GOFF_AH, GOFF_AL, Th, Tl, bm, sA, 0, tid);
        gemm_cpPre(sb, GOFF_BH, GOFF_BL, Bh, Bl, bn, K, 0, tid);
        CP_COMMIT();
    }
    for (int c = 0; c < NC; c++) {
        const int st = c & 1;
        const bool more = (c + 1 < NC);
        if (more) {
            const int k1 = (c + 1) * 32;
            uint32_t s1 = sb + ((c + 1) & 1) * GSTAGE;
            const unsigned short* Th = (k1 < Ksplit) ? A0h : A1h;
            const unsigned short* Tl = (k1 < Ksplit) ? A0l : A1l;
            const int kc = (k1 < Ksplit) ? k1 : (k1 - Ksplit);
            gemm_cpPre(s1, GOFF_AH, GOFF_AL, Th, Tl, bm, sA, kc, tid);
            gemm_cpPre(s1, GOFF_BH, GOFF_BL, Bh, Bl, bn, K, k1, tid);
            CP_COMMIT();
        }
        if (more) { CP_WAIT1(); } else { CP_WAIT0(); }
        __syncthreads();
        gemm_chunk(sb + st * GSTAGE, arow, brow, acc);
        __syncthreads();
    }
}

// ---------------------------------------------------------------------------
// Out projection: C fp32 row-major = A @ W + bias (A pre-split single source)
// ---------------------------------------------------------------------------
__global__ __launch_bounds__(256, 2) void mm_out(
    const unsigned short* __restrict__ Ahp, const unsigned short* __restrict__ Alp,
    const unsigned short* __restrict__ Bh, const unsigned short* __restrict__ Bl,
    const float* __restrict__ bias, float* __restrict__ C)
{
    extern __shared__ __align__(16) unsigned char smem[];
    const uint32_t sb = smem_u32(smem);
    const int tid = threadIdx.x, lane = tid & 31, wid = tid >> 5;
    const int wy = wid >> 2, wx = wid & 3;
    const int bn = blockIdx.x * 128, bm = blockIdx.y * 128;

    float acc[4][4][4];
#pragma unroll
    for (int i = 0; i < 4; i++)
#pragma unroll
        for (int j = 0; j < 4; j++)
#pragma unroll
            for (int q = 0; q < 4; q++) acc[i][j][q] = 0.f;

    const uint32_t arow = (wy * 64 + (lane & 15)) * 80 + (lane >> 4) * 16;
    const uint32_t brow = (wx * 32 + (lane & 15)) * 80 + (lane >> 4) * 16;

    gemm_main(sb, bm, bn, D_, D_, Ahp, Alp, D_, Ahp, Alp, Bh, Bl,
              tid, arow, brow, acc);

#pragma unroll
    for (int mt = 0; mt < 4; mt++) {
#pragma unroll
        for (int nt = 0; nt < 4; nt++) {
            int r0 = bm + wy * 64 + mt * 16 + (lane >> 2);
            int col = bn + wx * 32 + nt * 8 + 2 * (lane & 3);
            float b0 = bias[col], b1 = bias[col + 1];
            *(float2*)(C + (size_t)r0 * D_ + col) =
                make_float2(acc[mt][nt][0] + b0, acc[mt][nt][1] + b1);
            *(float2*)(C + (size_t)(r0 + 8) * D_ + col) =
                make_float2(acc[mt][nt][2] + b0, acc[mt][nt][3] + b1);
        }
    }
}

// ---------------------------------------------------------------------------
// Weight product: P = Wf[1024,512] @ W{q,k}[512,512], scaled (Q: 1/8),
// output TRANSPOSED + split: P^T [N=512][K=1024] bf16 hi/lo.
// grid (4, 8, 2): z=0 -> Pq (scale 1/8), z=1 -> Pk.
// ---------------------------------------------------------------------------
__global__ __launch_bounds__(256, 2) void wprod(
    const unsigned short* __restrict__ Ah, const unsigned short* __restrict__ Al,
    const unsigned short* __restrict__ Wqh, const unsigned short* __restrict__ Wql,
    const unsigned short* __restrict__ Wkh, const unsigned short* __restrict__ Wkl,
    unsigned short* __restrict__ Pqh, unsigned short* __restrict__ Pql,
    unsigned short* __restrict__ Pkh, unsigned short* __restrict__ Pkl)
{
    extern __shared__ __align__(16) unsigned char smem[];
    const uint32_t sb = smem_u32(smem);
    const int tid = threadIdx.x, lane = tid & 31, wid = tid >> 5;
    const int wy = wid >> 2, wx = wid & 3;
    const int bn = blockIdx.x * 128, bm = blockIdx.y * 128;
    const int z = blockIdx.z;
    const unsigned short* Bh = z ? Wkh : Wqh;
    const unsigned short* Bl = z ? Wkl : Wql;
    unsigned short* Ph = z ? Pkh : Pqh;
    unsigned short* Pl = z ? Pkl : Pql;
    const float sc = z ? 1.0f : 0.125f;

    float acc[4][4][4];
#pragma unroll
    for (int i = 0; i < 4; i++)
#pragma unroll
        for (int j = 0; j < 4; j++)
#pragma unroll
            for (int q = 0; q < 4; q++) acc[i][j][q] = 0.f;

    const uint32_t arow = (wy * 64 + (lane & 15)) * 80 + (lane >> 4) * 16;
    const uint32_t brow = (wx * 32 + (lane & 15)) * 80 + (lane >> 4) * 16;

    gemm_main(sb, bm, bn, D_, D_, Ah, Al, D_, Ah, Al, Bh, Bl,
              tid, arow, brow, acc);

#pragma unroll
    for (int mt = 0; mt < 4; mt++) {
#pragma unroll
        for (int nt = 0; nt < 4; nt++) {
            int r0 = bm + wy * 64 + mt * 16 + (lane >> 2);
            int col = bn + wx * 32 + nt * 8 + 2 * (lane & 3);
            unsigned short h, l;
            bsplit(acc[mt][nt][0] * sc, h, l);
            Ph[(size_t)col * (2 * D_) + r0] = h;
            Pl[(size_t)col * (2 * D_) + r0] = l;
            bsplit(acc[mt][nt][1] * sc, h, l);
            Ph[(size_t)(col + 1) * (2 * D_) + r0] = h;
            Pl[(size_t)(col + 1) * (2 * D_) + r0] = l;
            bsplit(acc[mt][nt][2] * sc, h, l);
            Ph[(size_t)col * (2 * D_) + r0 + 8] = h;
            Pl[(size_t)col * (2 * D_) + r0 + 8] = l;
            bsplit(acc[mt][nt][3] * sc, h, l);
            Ph[(size_t)(col + 1) * (2 * D_) + r0 + 8] = h;
            Pl[(size_t)(col + 1) * (2 * D_) + r0 + 8] = l;
        }
    }
}

// ---------------------------------------------------------------------------
// Q/K/V projection (fused stage folded away):
//   z=0: Q = X @ Pq + bfq   (K=1024, X = [gene||expr], pre-scaled 1/8)
//   z=1: K = X @ Pk + bfk   (K=1024)
//   z=2: V = expr @ Wv + bv (K=512)
// Output head-split bf16 hi/lo [B,H,S,HD].
// ---------------------------------------------------------------------------
__global__ __launch_bounds__(256, 2) void mm_qkv2(
    const unsigned short* __restrict__ Gh, const unsigned short* __restrict__ Gl,
    const unsigned short* __restrict__ Eh, const unsigned short* __restrict__ El,
    const unsigned short* __restrict__ Pqh, const unsigned short* __restrict__ Pql,
    const unsigned short* __restrict__ Pkh, const unsigned short* __restrict__ Pkl,
    const unsigned short* __restrict__ Wvh, const unsigned short* __restrict__ Wvl,
    const float* __restrict__ bfq, const float* __restrict__ bfk,
    const float* __restrict__ bv,
    unsigned short* __restrict__ Qh, unsigned short* __restrict__ Ql,
    unsigned short* __restrict__ Kh, unsigned short* __restrict__ Kl,
    unsigned short* __restrict__ Vh, unsigned short* __restrict__ Vl)
{
    extern __shared__ __align__(16) unsigned char smem[];
    const uint32_t sb = smem_u32(smem);
    const int tid = threadIdx.x, lane = tid & 31, wid = tid >> 5;
    const int wy = wid >> 2, wx = wid & 3;
    const int bn = blockIdx.x * 128, bm = blockIdx.y * 128;
    const int z = blockIdx.z;

    const unsigned short* A0h = (z == 2) ? Eh : Gh;
    const unsigned short* A0l = (z == 2) ? El : Gl;
    const unsigned short* Bh = (z == 0) ? Pqh : (z == 1) ? Pkh : Wvh;
    const unsigned short* Bl = (z == 0) ? Pql : (z == 1) ? Pkl : Wvl;
    const float* bias = (z == 0) ? bfq : (z == 1) ? bfk : bv;
    unsigned short* Ch = (z == 0) ? Qh : (z == 1) ? Kh : Vh;
    unsigned short* Cl = (z == 0) ? Ql : (z == 1) ? Kl : Vl;
    const int K = (z == 2) ? D_ : 2 * D_;

    float acc[4][4][4];
#pragma unroll
    for (int i = 0; i < 4; i++)
#pragma unroll
        for (int j = 0; j < 4; j++)
#pragma unroll
            for (int q = 0; q < 4; q++) acc[i][j][q] = 0.f;

    const uint32_t arow = (wy * 64 + (lane & 15)) * 80 + (lane >> 4) * 16;
    const uint32_t brow = (wx * 32 + (lane & 15)) * 80 + (lane >> 4) * 16;

    gemm_main(sb, bm, bn, K, D_, A0h, A0l, D_, Eh, El, Bh, Bl,
              tid, arow, brow, acc);

#pragma unroll
    for (int mt = 0; mt < 4; mt++) {
#pragma unroll
        for (int nt = 0; nt < 4; nt++) {
            int r0 = bm + wy * 64 + mt * 16 + (lane >> 2);
            int col = bn + wx * 32 + nt * 8 + 2 * (lane & 3);
            float b0 = bias[col], b1 = bias[col + 1];
            float2 v0 = make_float2(acc[mt][nt][0] + b0, acc[mt][nt][1] + b1);
            float2 v1 = make_float2(acc[mt][nt][2] + b0, acc[mt][nt][3] + b1);
            int hh = col >> 6, dd = col & (HD_ - 1);
            int bb0 = r0 >> 11, ss0 = r0 & (S_ - 1);
            size_t o0 = (((size_t)bb0 * H_ + hh) * S_ + ss0) * HD_ + dd;
            unsigned short hx, lx, hy, ly;
            bsplit(v0.x, hx, lx); bsplit(v0.y, hy, ly);
            *(ushort2*)(Ch + o0) = make_ushort2(hx, hy);
            *(ushort2*)(Cl + o0) = make_ushort2(lx, ly);
            int r1 = r0 + 8;
            int bb1 = r1 >> 11, ss1 = r1 & (S_ - 1);
            size_t o1 = (((size_t)bb1 * H_ + hh) * S_ + ss1) * HD_ + dd;
            bsplit(v1.x, hx, lx); bsplit(v1.y, hy, ly);
            *(ushort2*)(Ch + o1) = make_ushort2(hx, hy);
            *(ushort2*)(Cl + o1) = make_ushort2(lx, ly);
        }
    }
}

// ---------------------------------------------------------------------------
// Flash attention (R11/R15 structure — best measured). Unchanged.
// ---------------------------------------------------------------------------
#define AQ_H 0
#define AQ_L 18432
#define ASTG_BASE 36864
#define AS_KH 0
#define AS_KL 9216
#define AS_VH 18432
#define AS_VL 27648
#define AS_M  36864
#define MPITCH 304
#define ASTG  (36864 + 128 * MPITCH)        // 75776
#define ATTN_SMEM (36864 + 2 * ASTG)        // 188416

__device__ __forceinline__ void attn_cp_stage(
    uint32_t sb, int s,
    const unsigned short* Kh, const unsigned short* Kl,
    const unsigned short* Vh, const unsigned short* Vl,
    const float* Mp, size_t bhS, int q0, int kk0, int tid)
{
    const uint32_t base = sb + ASTG_BASE + s * ASTG;
#pragma unroll
    for (int i = 0; i < 8; i++) {
        const int t = i >> 1;
        const int idx = tid + (i & 1) * 256;
        const int row = idx >> 3, c16 = idx & 7;
        const unsigned short* sp = (t == 0) ? Kh : (t == 1) ? Kl
                                 : (t == 2) ? Vh : Vl;
        CP_ASYNC16(base + t * 9216 + row * 144 + c16 * 16,
                   (const char*)(sp + (bhS + kk0 + row) * HD_ + c16 * 8));
    }
#pragma unroll
    for (int i = 0; i < 8; i++) {
        const int idx = tid + i * 256;
        const int row = idx >> 4, c16 = idx & 15;
        CP_ASYNC16(base + AS_M + row * MPITCH + c16 * 16,
                   (const char*)(Mp + (size_t)(q0 + row) * S_ + kk0 + c16 * 4));
    }
}

__global__ __launch_bounds__(256, 1) void attn_mma(
    const unsigned short* __restrict__ Qh, const unsigned short* __restrict__ Ql,
    const unsigned short* __restrict__ Kh, const unsigned short* __restrict__ Kl,
    const unsigned short* __restrict__ Vh, const unsigned short* __restrict__ Vl,
    const float* __restrict__ Mm,
    unsigned short* __restrict__ Oh, unsigned short* __restrict__ Ol)
{
    extern __shared__ __align__(16) unsigned char smem[];
    const uint32_t sb = smem_u32(smem);

    const int q0 = blockIdx.x * 128;
    const int h  = blockIdx.y;
    const int b  = blockIdx.z;
    const int tid = threadIdx.x, lane = tid & 31, w = tid >> 5;
    const int qr = lane >> 2, qc = lane & 3;

    const size_t bhS = ((size_t)b * H_ + h) * S_;
    const float* Mp = Mm + (size_t)b * S_ * S_;

#pragma unroll
    for (int i = 0; i < 8; i++) {
        const int idx = tid + (i & 3) * 256;
        const int row = idx >> 3, c16 = idx & 7;
        const unsigned short* sp = (i < 4) ? Qh : Ql;
        const uint32_t off = (i < 4) ? AQ_H : AQ_L;
        CP_ASYNC16(sb + off + row * 144 + c16 * 16,
                   (const char*)(sp + (bhS + q0 + row) * HD_ + c16 * 8));
    }
    attn_cp_stage(sb, 0, Kh, Kl, Vh, Vl, Mp, bhS, q0, 0, tid);
    CP_COMMIT();

    float O[8][4];
#pragma unroll
    for (int t = 0; t < 8; t++)
#pragma unroll
        for (int j = 0; j < 4; j++) O[t][j] = 0.f;
    float m0 = -1e30f, m1 = -1e30f, Z0 = 0.f, Z1 = 0.f, T0 = 0.f, T1 = 0.f;

    const uint32_t qrow = (w * 16 + (lane & 15)) * 144 + (lane >> 4) * 16;
    const uint32_t klrow = (lane & 15) * 144 + (lane >> 4) * 16;

    uint32_t qah[4][4], qal[4][4];

    const int NB = S_ / 64;
    for (int kb = 0; kb < NB; kb++) {
        const int st = kb & 1;
        const bool more = (kb + 1 < NB);
        if (more) {
            attn_cp_stage(sb, st ^ 1, Kh, Kl, Vh, Vl, Mp, bhS, q0,
                          (kb + 1) * 64, tid);
            CP_COMMIT();
            CP_WAIT1();
        } else {
            CP_WAIT0();
        }
        __syncthreads();

        if (kb == 0) {
#pragma unroll
            for (int ks = 0; ks < 4; ks++) {
                ldm4(sb + AQ_H + qrow + ks * 32, qah[ks]);
                ldm4(sb + AQ_L + qrow + ks * 32, qal[ks]);
            }
        }

        const uint32_t stg = sb + ASTG_BASE + st * ASTG;

        float S[8][4];
#pragma unroll
        for (int t = 0; t < 8; t++)
#pragma unroll
            for (int j = 0; j < 4; j++) S[t][j] = 0.f;
#pragma unroll
        for (int ks = 0; ks < 4; ks++) {
#pragma unroll
            for (int nb = 0; nb < 4; nb++) {
                uint32_t bh4[4], bl4[4];
                ldm4(stg + AS_KH + klrow + nb * 2304 + ks * 32, bh4);
                ldm4(stg + AS_KL + klrow + nb * 2304 + ks * 32, bl4);
                uint32_t th0[2] = {bh4[0], bh4[2]}, th1[2] = {bh4[1], bh4[3]};
                uint32_t tl0[2] = {bl4[0], bl4[2]}, tl1[2] = {bl4[1], bl4[3]};
                mma_bf16(S[2 * nb],     qah[ks], th0);
                mma_bf16(S[2 * nb + 1], qah[ks], th1);
                mma_bf16(S[2 * nb],     qah[ks], tl0);
                mma_bf16(S[2 * nb + 1], qah[ks], tl1);
                mma_bf16(S[2 * nb],     qal[ks], th0);
                mma_bf16(S[2 * nb + 1], qal[ks], th1);
            }
        }

        const unsigned char* msp = smem + ASTG_BASE + st * ASTG + AS_M;
        const int mr0 = (w * 16 + qr) * MPITCH + qc * 8;
        float bm0 = -1e30f, bm1 = -1e30f;
        float mva[8], mvb[8], mvc[8], mvd[8];
#pragma unroll
        for (int t = 0; t < 8; t++) {
            float2 ma = *(const float2*)(msp + mr0 + t * 32);
            float2 mb = *(const float2*)(msp + mr0 + 8 * MPITCH + t * 32);
            mva[t] = ma.x; mvb[t] = ma.y; mvc[t] = mb.x; mvd[t] = mb.y;
            S[t][0] *= ma.x;
            S[t][1] *= ma.y;
            S[t][2] *= mb.x;
            S[t][3] *= mb.y;
            bm0 = fmaxf(bm0, fmaxf(S[t][0], S[t][1]));
            bm1 = fmaxf(bm1, fmaxf(S[t][2], S[t][3]));
        }
        bm0 = fmaxf(bm0, __shfl_xor_sync(0xffffffffu, bm0, 1));
        bm0 = fmaxf(bm0, __shfl_xor_sync(0xffffffffu, bm0, 2));
        bm1 = fmaxf(bm1, __shfl_xor_sync(0xffffffffu, bm1, 1));
        bm1 = fmaxf(bm1, __shfl_xor_sync(0xffffffffu, bm1, 2));
        if (bm0 > m0) {
            float f0 = __expf(m0 - bm0);
            m0 = bm0; Z0 *= f0; T0 *= f0;
#pragma unroll
            for (int t = 0; t < 8; t++) { O[t][0] *= f0; O[t][1] *= f0; }
        }
        if (bm1 > m1) {
            float f1 = __expf(m1 - bm1);
            m1 = bm1; Z1 *= f1; T1 *= f1;
#pragma unroll
            for (int t = 0; t < 8; t++) { O[t][2] *= f1; O[t][3] *= f1; }
        }
#pragma unroll
        for (int t = 0; t < 8; t++) {
            float e0 = __expf(S[t][0] - m0);
            float e1 = __expf(S[t][1] - m0);
            float e2 = __expf(S[t][2] - m1);
            float e3 = __expf(S[t][3] - m1);
            Z0 += e0 + e1; Z1 += e2 + e3;
            float p0 = e0 * mva[t], p1 = e1 * mvb[t];
            float p2 = e2 * mvc[t], p3 = e3 * mvd[t];
            T0 += p0 + p1; T1 += p2 + p3;
            S[t][0] = p0; S[t][1] = p1; S[t][2] = p2; S[t][3] = p3;
        }

        uint32_t phi[4][4], plo[4][4];
#pragma unroll
        for (int kt = 0; kt < 4; kt++) {
            pack2(S[2 * kt][0],     S[2 * kt][1],     phi[kt][0], plo[kt][0]);
            pack2(S[2 * kt][2],     S[2 * kt][3],     phi[kt][1], plo[kt][1]);
            pack2(S[2 * kt + 1][0], S[2 * kt + 1][1], phi[kt][2], plo[kt][2]);
            pack2(S[2 * kt + 1][2], S[2 * kt + 1][3], phi[kt][3], plo[kt][3]);
        }

#pragma unroll
        for (int kt = 0; kt < 4; kt++) {
#pragma unroll
            for (int nb = 0; nb < 4; nb++) {
                uint32_t vh4[4], vl4[4];
                ldm4t(stg + AS_VH + kt * 2304 + klrow + nb * 32, vh4);
                ldm4t(stg + AS_VL + kt * 2304 + klrow + nb * 32, vl4);
                uint32_t th0[2] = {vh4[0], vh4[1]}, th1[2] = {vh4[2], vh4[3]};
                uint32_t tl0[2] = {vl4[0], vl4[1]}, tl1[2] = {vl4[2], vl4[3]};
                mma_bf16(O[2 * nb],     phi[kt], th0);
                mma_bf16(O[2 * nb + 1], phi[kt], th1);
                mma_bf16(O[2 * nb],     phi[kt], tl0);
                mma_bf16(O[2 * nb + 1], phi[kt], tl1);
                mma_bf16(O[2 * nb],     plo[kt], th0);
                mma_bf16(O[2 * nb + 1], plo[kt], th1);
            }
        }
        __syncthreads();
    }

    T0 += __shfl_xor_sync(0xffffffffu, T0, 1);
    T0 += __shfl_xor_sync(0xffffffffu, T0, 2);
    T1 += __shfl_xor_sync(0xffffffffu, T1, 1);
    T1 += __shfl_xor_sync(0xffffffffu, T1, 2);
    Z0 += __shfl_xor_sync(0xffffffffu, Z0, 1);
    Z0 += __shfl_xor_sync(0xffffffffu, Z0, 2);
    Z1 += __shfl_xor_sync(0xffffffffu, Z1, 1);
    Z1 += __shfl_xor_sync(0xffffffffu, Z1, 2);
    float inv0 = 1.0f / (T0 + EPS_ * Z0);
    float inv1 = 1.0f / (T1 + EPS_ * Z1);

    int gr0 = q0 + w * 16 + qr;
#pragma unroll
    for (int t = 0; t < 8; t++) {
        int d = t * 8 + 2 * qc;
        size_t o0 = ((size_t)b * S_ + gr0) * D_ + h * HD_ + d;
        size_t o1 = ((size_t)b * S_ + gr0 + 8) * D_ + h * HD_ + d;
        uint32_t h2, l2;
        pack2(O[t][0] * inv0, O[t][1] * inv0, h2, l2);
        *(uint32_t*)(Oh + o0) = h2;
        *(uint32_t*)(Ol + o0) = l2;
        pack2(O[t][2] * inv1, O[t][3] * inv1, h2, l2);
        *(uint32_t*)(Oh + o1) = h2;
        *(uint32_t*)(Ol + o1) = l2;
    }
}

// ---------------------------------------------------------------------------
// Host
// ---------------------------------------------------------------------------
extern "C" void kernel_launch(void* const* d_in, const int* in_sizes, int n_in,
                              void* d_out, int out_size)
{
    const float* gene = (const float*)d_in[0];
    const float* expr = (const float*)d_in[1];
    const float* Mm   = (const float*)d_in[2];
    const float* Wf   = (const float*)d_in[3];
    const float* bf   = (const float*)d_in[4];
    const float* Wq   = (const float*)d_in[5];
    const float* bq   = (const float*)d_in[6];
    const float* Wk   = (const float*)d_in[7];
    const float* bk   = (const float*)d_in[8];
    const float* Wv   = (const float*)d_in[9];
    const float* bv   = (const float*)d_in[10];
    const float* Wo   = (const float*)d_in[11];
    const float* bo   = (const float*)d_in[12];
    float* out = (float*)d_out;

    unsigned short *Gh, *Gl, *Eh, *El, *Qh, *Ql, *Kh, *Kl, *Vh, *Vl;
    unsigned short *Ahb, *Alb, *Wfh, *Wfl;
    unsigned short *Wqh, *Wql, *Wkh, *Wkl, *Wvh, *Wvl, *Woh, *Wol;
    unsigned short *Pqh, *Pql, *Pkh, *Pkl;
    float *bfq, *bfk;
    cudaGetSymbolAddress((void**)&Gh,  g_Gh);
    cudaGetSymbolAddress((void**)&Gl,  g_Gl);
    cudaGetSymbolAddress((void**)&Eh,  g_Eh);
    cudaGetSymbolAddress((void**)&El,  g_El);
    cudaGetSymbolAddress((void**)&Qh,  g_Qh);
    cudaGetSymbolAddress((void**)&Ql,  g_Ql);
    cudaGetSymbolAddress((void**)&Kh,  g_Kh);
    cudaGetSymbolAddress((void**)&Kl,  g_Kl);
    cudaGetSymbolAddress((void**)&Vh,  g_Vh);
    cudaGetSymbolAddress((void**)&Vl,  g_Vl);
    cudaGetSymbolAddress((void**)&Ahb, g_Ah);
    cudaGetSymbolAddress((void**)&Alb, g_Al);
    cudaGetSymbolAddress((void**)&Wfh, g_Wfrm_h);
    cudaGetSymbolAddress((void**)&Wfl, g_Wfrm_l);
    cudaGetSymbolAddress((void**)&Wqh, g_Wq_h);
    cudaGetSymbolAddress((void**)&Wql, g_Wq_l);
    cudaGetSymbolAddress((void**)&Wkh, g_Wk_h);
    cudaGetSymbolAddress((void**)&Wkl, g_Wk_l);
    cudaGetSymbolAddress((void**)&Wvh, g_Wv_h);
    cudaGetSymbolAddress((void**)&Wvl, g_Wv_l);
    cudaGetSymbolAddress((void**)&Woh, g_Wo_h);
    cudaGetSymbolAddress((void**)&Wol, g_Wo_l);
    cudaGetSymbolAddress((void**)&Pqh, g_Pq_h);
    cudaGetSymbolAddress((void**)&Pql, g_Pq_l);
    cudaGetSymbolAddress((void**)&Pkh, g_Pk_h);
    cudaGetSymbolAddress((void**)&Pkl, g_Pk_l);
    cudaGetSymbolAddress((void**)&bfq, g_bfq);
    cudaGetSymbolAddress((void**)&bfk, g_bfk);

    cudaFuncSetAttribute(wprod,   cudaFuncAttributeMaxDynamicSharedMemorySize, GM_SMEM);
    cudaFuncSetAttribute(mm_qkv2, cudaFuncAttributeMaxDynamicSharedMemorySize, GM_SMEM);
    cudaFuncSetAttribute(mm_out,  cudaFuncAttributeMaxDynamicSharedMemorySize, GM_SMEM);
    cudaFuncSetAttribute(attn_mma, cudaFuncAttributeMaxDynamicSharedMemorySize, ATTN_SMEM);

    // 1) preconversions (independent)
    split_in<<<ROWS_ * D_ / 4 / 256, 256>>>(gene, expr, Gh, Gl, Eh, El);
    split_wf<<<(2 * D_) * D_ / 4 / 256, 256>>>(Wf, Wfh, Wfl);
    wconv_all<<<dim3(16, 16, 4), dim3(32, 32)>>>(
        Wq, Wk, Wv, Wo,
        Wqh, Wql, Wkh, Wkl, Wvh, Wvl, Woh, Wol);
    bias_fold<<<dim3(64, 2), 256>>>(bf, Wq, Wk, bq, bk, bfq, bfk);

    // 2) weight products Pq = (Wf@Wq)/8, Pk = Wf@Wk  (transposed hi/lo)
    wprod<<<dim3(4, 8, 2), 256, GM_SMEM>>>(Wfh, Wfl, Wqh, Wql, Wkh, Wkl,
                                           Pqh, Pql, Pkh, Pkl);

    // 3) Q, K (K=1024, fused folded) and V (K=512) in ONE launch
    mm_qkv2<<<dim3(4, 64, 3), 256, GM_SMEM>>>(Gh, Gl, Eh, El,
                                              Pqh, Pql, Pkh, Pkl, Wvh, Wvl,
                                              bfq, bfk, bv,
                                              Qh, Ql, Kh, Kl, Vh, Vl);

    // 4) flash attention (unchanged), bf16 hi/lo output
    attn_mma<<<dim3(S_ / 128, H_, B_), 256, ATTN_SMEM>>>(Qh, Ql, Kh, Kl,
                                                         Vh, Vl, Mm,
                                                         Ahb, Alb);

    // 5) out = attn @ Wo + bo
    mm_out<<<dim3(D_ / 128, ROWS_ / 128), 256, GM_SMEM>>>(Ahb, Alb, Woh, Wol,
                                                          bo, out);
}